// round 2
// baseline (speedup 1.0000x reference)
#include <cuda_runtime.h>
#include <math.h>

#define BB 2
#define NN 32768
#define KK 16
#define TILE 64
#define NTHR 512
#define NBLK (BB * (NN / TILE))

// Transposed net_new scratch: (B, N, 64) so a neighbor's feature vector is 256B contiguous.
__device__ float g_netT[(size_t)BB * NN * 64];

// ---------------------------------------------------------------------------
// Activation
// ---------------------------------------------------------------------------
template <int ACT>
__device__ __forceinline__ float actf(float v) {
    if (ACT == 1) return v > 0.f ? v : 0.f;           // relu
    if (ACT == 2) return 1.f / (1.f + __expf(-v));    // sigmoid
    if (ACT == 3) return tanhf(v);                    // tanh
    return v;
}

// ---------------------------------------------------------------------------
// Load per-stage weights (O x C row-major in global) into SMEM transposed:
// sW[c*68 + o].  Rows o >= O are zero-filled (lets us always compute 64 rows).
// Global reads are coalesced along c; SMEM stores are stride-68 (<=8-way).
// ---------------------------------------------------------------------------
__device__ __forceinline__ void load_w(const float* __restrict__ w, int O, int C,
                                       float* __restrict__ sW) {
    for (int idx = threadIdx.x; idx < 64 * C; idx += NTHR) {
        int o = idx / C;
        int c = idx - o * C;
        float v = 0.f;
        if (o < O) v = w[o * C + c];
        sW[c * 68 + o] = v;
    }
}

// Load a 64-channel tile from a (B, 64, N) tensor into SMEM [64][64].
__device__ __forceinline__ void load_cn(const float* __restrict__ g, int b, int n0,
                                        float* __restrict__ dst) {
    for (int idx = threadIdx.x; idx < 64 * 64; idx += NTHR) {
        int c = idx >> 6, t = idx & 63;
        dst[idx] = g[(size_t)(b * 64 + c) * NN + n0 + t];
    }
}

// ---------------------------------------------------------------------------
// Tile GEMM: yb[o][t] = act( sum_c sW[c][o] * xb[c][t] + bias[o] )
// 512 threads: each owns (2 outputs o0,o0+1) x (4 points t0..t0+3).
// VEC=1 -> xstride multiple of 4, use float4 input loads.
// ---------------------------------------------------------------------------
template <int ACT, int VEC>
__device__ __forceinline__ void gemm64(const float* __restrict__ xb, int xstride, int C,
                                       const float* __restrict__ sW,
                                       const float* __restrict__ gb, int O,
                                       float* __restrict__ yb) {
    const int tid = threadIdx.x;
    const int o0 = (tid >> 4) << 1;   // 0..62 step 2
    const int t0 = (tid & 15) << 2;   // 0..60 step 4

    float a0 = 0.f, a1 = 0.f, a2 = 0.f, a3 = 0.f;
    float b0 = 0.f, b1 = 0.f, b2 = 0.f, b3 = 0.f;

#pragma unroll 4
    for (int c = 0; c < C; c++) {
        float2 w = *(const float2*)(sW + c * 68 + o0);
        float x0, x1, x2, x3;
        if (VEC) {
            float4 xv = *(const float4*)(xb + c * xstride + t0);
            x0 = xv.x; x1 = xv.y; x2 = xv.z; x3 = xv.w;
        } else {
            const float* xr = xb + c * xstride + t0;
            x0 = xr[0]; x1 = xr[1]; x2 = xr[2]; x3 = xr[3];
        }
        a0 = fmaf(w.x, x0, a0); a1 = fmaf(w.x, x1, a1);
        a2 = fmaf(w.x, x2, a2); a3 = fmaf(w.x, x3, a3);
        b0 = fmaf(w.y, x0, b0); b1 = fmaf(w.y, x1, b1);
        b2 = fmaf(w.y, x2, b2); b3 = fmaf(w.y, x3, b3);
    }

    if (o0 < O) {
        float bs = gb[o0];
        float* yr = yb + o0 * 64 + t0;
        yr[0] = actf<ACT>(a0 + bs); yr[1] = actf<ACT>(a1 + bs);
        yr[2] = actf<ACT>(a2 + bs); yr[3] = actf<ACT>(a3 + bs);
    }
    if (o0 + 1 < O) {
        float bs = gb[o0 + 1];
        float* yr = yb + (o0 + 1) * 64 + t0;
        yr[0] = actf<ACT>(b0 + bs); yr[1] = actf<ACT>(b1 + bs);
        yr[2] = actf<ACT>(b2 + bs); yr[3] = actf<ACT>(b3 + bs);
    }
}

// ---------------------------------------------------------------------------
// Kernel A: MotionEncoder + ConvGRU  ->  net_new (d_out) + g_netT (transposed)
// SMEM floats: X[192*64] Y[4096] Z[4096] Nn[4096] W[192*68] FL[192]  = 37824
// ---------------------------------------------------------------------------
#define SMEMA_FLOATS 37824

__global__ void __launch_bounds__(NTHR, 1) kernelA(
    const float* __restrict__ net, const float* __restrict__ inp,
    const float* __restrict__ corr, const float* __restrict__ flow,
    const float* __restrict__ w_corr, const float* __restrict__ b_corr,
    const float* __restrict__ w_flow, const float* __restrict__ b_flow,
    const float* __restrict__ w_me, const float* __restrict__ b_me,
    const float* __restrict__ wz, const float* __restrict__ bz,
    const float* __restrict__ wr, const float* __restrict__ br,
    const float* __restrict__ wq, const float* __restrict__ bq,
    float* __restrict__ out_net) {
    extern __shared__ float sm[];
    float* X  = sm;            // 192*64 = 12288
    float* Y  = sm + 12288;    // 4096
    float* Z  = sm + 16384;    // 4096
    float* Nn = sm + 20480;    // 4096
    float* W  = sm + 24576;    // 192*68 = 13056
    float* FL = sm + 37632;    // 192

    const int tid = threadIdx.x;
    const int b = blockIdx.x / (NN / TILE);
    const int n0 = (blockIdx.x % (NN / TILE)) * TILE;

    // ---- stage 0: load tiles ----
    load_cn(corr, b, n0, X);   // X rows 0..63 = corr
    load_cn(net, b, n0, Nn);
    for (int idx = tid; idx < 192; idx += NTHR)
        FL[idx] = flow[(size_t)(b * NN + n0) * 3 + idx];
    load_w(w_corr, 64, 64, W);
    __syncthreads();

    // flo -> X rows 64..127 (tiny matvec, independent of rows 0..63)
    for (int idx = tid; idx < 4096; idx += NTHR) {
        int o = idx >> 6, t = idx & 63;
        float v = b_flow[o];
        v = fmaf(w_flow[o * 3 + 0], FL[t * 3 + 0], v);
        v = fmaf(w_flow[o * 3 + 1], FL[t * 3 + 1], v);
        v = fmaf(w_flow[o * 3 + 2], FL[t * 3 + 2], v);
        X[(64 + o) * 64 + t] = fmaxf(v, 0.f);
    }
    // cor = relu(Wcorr @ corr)
    gemm64<1, 1>(X, 64, 64, W, b_corr, 64, Y);
    __syncthreads();

    // ---- mf = relu(Wme @ [cor; flo]) ----
    for (int idx = tid; idx < 4096; idx += NTHR) X[idx] = Y[idx];  // cor -> rows 0..63
    load_w(w_me, 61, 128, W);
    __syncthreads();
    gemm64<1, 1>(X, 64, 128, W, b_me, 61, Y);
    __syncthreads();

    // ---- build hx = [net | inp | mf | flow] ----
    for (int idx = tid; idx < 4096; idx += NTHR) X[idx] = Nn[idx];
    load_cn(inp, b, n0, X + 64 * 64);
    for (int idx = tid; idx < 61 * 64; idx += NTHR) X[128 * 64 + idx] = Y[idx];
    for (int idx = tid; idx < 192; idx += NTHR) {
        int t = idx / 3, d = idx - t * 3;
        X[(189 + d) * 64 + t] = FL[idx];
    }
    load_w(wz, 64, 192, W);
    __syncthreads();
    gemm64<2, 1>(X, 64, 192, W, bz, 64, Z);     // z
    __syncthreads();
    load_w(wr, 64, 192, W);
    __syncthreads();
    gemm64<2, 1>(X, 64, 192, W, br, 64, Y);     // r
    __syncthreads();
    for (int idx = tid; idx < 4096; idx += NTHR) X[idx] = Y[idx] * Nn[idx];  // r*net
    load_w(wq, 64, 192, W);
    __syncthreads();
    gemm64<3, 1>(X, 64, 192, W, bq, 64, Y);     // q
    __syncthreads();

    // ---- net_new = (1-z)*net + z*q ----
    for (int idx = tid; idx < 4096; idx += NTHR) {
        int o = idx >> 6, t = idx & 63;
        float z = Z[idx];
        float v = fmaf(z, Y[idx] - Nn[idx], Nn[idx]);  // (1-z)*n + z*q
        X[idx] = v;
        out_net[(size_t)(b * 64 + o) * NN + n0 + t] = v;
    }
    __syncthreads();
    // transposed copy for neighbor gather
    for (int idx = tid; idx < 4096; idx += NTHR) {
        int t = idx >> 6, o = idx & 63;
        g_netT[(size_t)(b * NN + n0 + t) * 64 + o] = X[o * 64 + t];
    }
}

// ---------------------------------------------------------------------------
// Kernel B: FlowHead (o1, SetConv over K=16 neighbors, out MLP) -> delta
// SMEM floats: X[8192] XG[4360] Y[4096] O1[4096] MX[4096] W[8704] EF[3072] E[1024]
// ---------------------------------------------------------------------------
#define SMEMB_FLOATS 37640

__global__ void __launch_bounds__(NTHR, 1) kernelB(
    const float* __restrict__ out_net, const int* __restrict__ edges,
    const float* __restrict__ ef,
    const float* __restrict__ w_fh1, const float* __restrict__ b_fh1,
    const float* __restrict__ w_sc1, const float* __restrict__ b_sc1,
    const float* __restrict__ w_sc2, const float* __restrict__ b_sc2,
    const float* __restrict__ w_sc3, const float* __restrict__ b_sc3,
    const float* __restrict__ w_out1, const float* __restrict__ b_out1,
    const float* __restrict__ w_out2, const float* __restrict__ b_out2,
    float* __restrict__ out_delta) {
    extern __shared__ float sm[];
    float* X  = sm;            // 128*64 = 8192
    float* XG = sm + 8192;     // 67*65 = 4355 (pad 4360)
    float* Y  = sm + 12552;    // 4096
    float* O1 = sm + 16648;    // 4096
    float* MX = sm + 20744;    // 4096
    float* W  = sm + 24840;    // 128*68 = 8704
    float* EF = sm + 33544;    // 3072
    int*   E  = (int*)(sm + 36616);  // 1024 ints

    const int tid = threadIdx.x;
    const int b = blockIdx.x / (NN / TILE);
    const int n0 = (blockIdx.x % (NN / TILE)) * TILE;

    load_cn(out_net, b, n0, X);  // net_new tile
    for (int idx = tid; idx < TILE * KK; idx += NTHR)
        E[idx] = edges[(size_t)(b * NN + n0) * KK + idx];
    for (int idx = tid; idx < TILE * KK * 3; idx += NTHR)
        EF[idx] = ef[(size_t)(b * NN + n0) * KK * 3 + idx];
    load_w(w_fh1, 64, 64, W);
    __syncthreads();
    gemm64<0, 1>(X, 64, 64, W, b_fh1, 64, O1);   // o1 (no activation)
    __syncthreads();
    load_w(w_sc1, 64, 67, W);

    const float4* gT = reinterpret_cast<const float4*>(g_netT);

    // ---- SetConv stage 1 + max over K ----
    for (int k = 0; k < KK; k++) {
        __syncthreads();  // prev gemm done reading XG; W ready on k==0
        // gather neighbor features -> XG rows 0..63 (stride 65)
        for (int f = tid; f < TILE * 16; f += NTHR) {
            int c4 = f & 15, t = f >> 4;
            int e = E[t * KK + k];
            float4 v = __ldg(gT + (size_t)(b * NN + e) * 16 + c4);
            int c = c4 * 4;
            XG[(c + 0) * 65 + t] = v.x;
            XG[(c + 1) * 65 + t] = v.y;
            XG[(c + 2) * 65 + t] = v.z;
            XG[(c + 3) * 65 + t] = v.w;
        }
        // edge feats -> XG rows 64..66
        for (int idx = tid; idx < 192; idx += NTHR) {
            int t = idx / 3, d = idx - t * 3;
            XG[(64 + d) * 65 + t] = EF[(t * KK + k) * 3 + d];
        }
        __syncthreads();
        gemm64<1, 0>(XG, 65, 67, W, b_sc1, 64, Y);
        __syncthreads();
        if (k == 0) {
            for (int idx = tid; idx < 4096; idx += NTHR) MX[idx] = Y[idx];
        } else {
            for (int idx = tid; idx < 4096; idx += NTHR) MX[idx] = fmaxf(MX[idx], Y[idx]);
        }
    }
    __syncthreads();

    // ---- sc2, sc3 ----
    load_w(w_sc2, 64, 64, W);
    __syncthreads();
    gemm64<1, 1>(MX, 64, 64, W, b_sc2, 64, Y);
    __syncthreads();
    load_w(w_sc3, 64, 64, W);
    __syncthreads();
    gemm64<1, 1>(Y, 64, 64, W, b_sc3, 64, X);    // sc -> X rows 0..63
    __syncthreads();

    // ---- out MLP: o = relu(Wout1 @ [sc; o1]); delta = Wout2 @ o ----
    for (int idx = tid; idx < 4096; idx += NTHR) X[64 * 64 + idx] = O1[idx];
    load_w(w_out1, 64, 128, W);
    __syncthreads();
    gemm64<1, 1>(X, 64, 128, W, b_out1, 64, Y);
    __syncthreads();
    load_w(w_out2, 3, 64, W);
    __syncthreads();
    gemm64<0, 1>(Y, 64, 64, W, b_out2, 3, MX);   // delta rows 0..2
    __syncthreads();
    for (int idx = tid; idx < 192; idx += NTHR) {
        int t = idx / 3, d = idx - t * 3;
        out_delta[(size_t)(b * NN + n0 + t) * 3 + d] = MX[d * 64 + t];
    }
}

// ---------------------------------------------------------------------------
// Launch
// ---------------------------------------------------------------------------
extern "C" void kernel_launch(void* const* d_in, const int* in_sizes, int n_in,
                              void* d_out, int out_size) {
    const float* net       = (const float*)d_in[0];
    const float* inp       = (const float*)d_in[1];
    const float* corr      = (const float*)d_in[2];
    const float* flow      = (const float*)d_in[3];
    const int*   edges     = (const int*)d_in[4];
    const float* edgef     = (const float*)d_in[5];
    const float* w_corr    = (const float*)d_in[6];
    const float* b_corr    = (const float*)d_in[7];
    const float* w_flow    = (const float*)d_in[8];
    const float* b_flow    = (const float*)d_in[9];
    const float* w_me      = (const float*)d_in[10];
    const float* b_me      = (const float*)d_in[11];
    const float* wz        = (const float*)d_in[12];
    const float* bz        = (const float*)d_in[13];
    const float* wr        = (const float*)d_in[14];
    const float* br        = (const float*)d_in[15];
    const float* wq        = (const float*)d_in[16];
    const float* bq        = (const float*)d_in[17];
    const float* w_fh1     = (const float*)d_in[18];
    const float* b_fh1     = (const float*)d_in[19];
    const float* w_sc1     = (const float*)d_in[20];
    const float* b_sc1     = (const float*)d_in[21];
    const float* w_sc2     = (const float*)d_in[22];
    const float* b_sc2     = (const float*)d_in[23];
    const float* w_sc3     = (const float*)d_in[24];
    const float* b_sc3     = (const float*)d_in[25];
    const float* w_out1    = (const float*)d_in[26];
    const float* b_out1    = (const float*)d_in[27];
    const float* w_out2    = (const float*)d_in[28];
    const float* b_out2    = (const float*)d_in[29];

    float* out_net   = (float*)d_out;
    float* out_delta = (float*)d_out + (size_t)BB * 64 * NN;

    const int smemA = SMEMA_FLOATS * 4;
    const int smemB = SMEMB_FLOATS * 4;
    cudaFuncSetAttribute(kernelA, cudaFuncAttributeMaxDynamicSharedMemorySize, smemA);
    cudaFuncSetAttribute(kernelB, cudaFuncAttributeMaxDynamicSharedMemorySize, smemB);

    kernelA<<<NBLK, NTHR, smemA>>>(net, inp, corr, flow,
                                   w_corr, b_corr, w_flow, b_flow, w_me, b_me,
                                   wz, bz, wr, br, wq, bq, out_net);
    kernelB<<<NBLK, NTHR, smemB>>>(out_net, edges, edgef,
                                   w_fh1, b_fh1, w_sc1, b_sc1, w_sc2, b_sc2,
                                   w_sc3, b_sc3, w_out1, b_out1, w_out2, b_out2,
                                   out_delta);
}

// round 5
// speedup vs baseline: 1.3600x; 1.3600x over previous
#include <cuda_runtime.h>
#include <math.h>
#include <float.h>

#define BB 2
#define NN 32768
#define KK 16
#define TILE 64
#define NTHR 256
#define NBLK (BB * (NN / TILE))

// Scratch: tpre = W1a @ net_new, transposed (B,N,64) for 256B-contiguous gather.
__device__ float g_preT[(size_t)BB * NN * 64];
// Scratch: o1 = w_fh1 @ net_new + b, layout (B,64,N).
__device__ float g_o1[(size_t)BB * 64 * NN];

// ---------------------------------------------------------------------------
// Activation
// ---------------------------------------------------------------------------
template <int ACT>
__device__ __forceinline__ float actf(float v) {
    if (ACT == 1) return v > 0.f ? v : 0.f;           // relu
    if (ACT == 2) return 1.f / (1.f + __expf(-v));    // sigmoid
    if (ACT == 3) return tanhf(v);                    // tanh
    return v;
}

// ---------------------------------------------------------------------------
// Stage weights (O x ld row-major, first C cols used) -> SMEM transposed
// sW[c*68 + o], rows o >= O zero-filled.
// ---------------------------------------------------------------------------
__device__ __forceinline__ void load_w(const float* __restrict__ w, int O, int C,
                                       int ld, float* __restrict__ sW) {
    for (int idx = threadIdx.x; idx < 64 * C; idx += NTHR) {
        int o = idx / C;
        int c = idx - o * C;
        float v = 0.f;
        if (o < O) v = w[o * ld + c];
        sW[c * 68 + o] = v;
    }
}

// Load a 64-channel tile from a (B, 64, N) tensor into SMEM [64][64].
__device__ __forceinline__ void load_cn(const float* __restrict__ g, int b, int n0,
                                        float* __restrict__ dst) {
    for (int idx = threadIdx.x; idx < 64 * 64; idx += NTHR) {
        int c = idx >> 6, t = idx & 63;
        dst[idx] = g[(size_t)(b * 64 + c) * NN + n0 + t];
    }
}

// ---------------------------------------------------------------------------
// Tile GEMM: yb[o][t] = act( sum_c sW[c][o] * xb[c][t] + bias[o] )
// 256 threads, each owns 4 outputs x 4 points: per c-iter 2 LDS.128 : 16 FFMA.
// xb stride fixed at 64 floats (float4 aligned).  gb == nullptr -> no bias.
// ---------------------------------------------------------------------------
template <int ACT>
__device__ __forceinline__ void gemm64(const float* __restrict__ xb, int C,
                                       const float* __restrict__ sW,
                                       const float* __restrict__ gb, int O,
                                       float* __restrict__ yb) {
    const int tid = threadIdx.x;
    const int o0 = (tid >> 4) << 2;   // 0..60 step 4
    const int t0 = (tid & 15) << 2;   // 0..60 step 4

    float a00 = 0.f, a01 = 0.f, a02 = 0.f, a03 = 0.f;
    float a10 = 0.f, a11 = 0.f, a12 = 0.f, a13 = 0.f;
    float a20 = 0.f, a21 = 0.f, a22 = 0.f, a23 = 0.f;
    float a30 = 0.f, a31 = 0.f, a32 = 0.f, a33 = 0.f;

#pragma unroll 4
    for (int c = 0; c < C; c++) {
        float4 w = *(const float4*)(sW + c * 68 + o0);
        float4 x = *(const float4*)(xb + c * 64 + t0);
        a00 = fmaf(w.x, x.x, a00); a01 = fmaf(w.x, x.y, a01);
        a02 = fmaf(w.x, x.z, a02); a03 = fmaf(w.x, x.w, a03);
        a10 = fmaf(w.y, x.x, a10); a11 = fmaf(w.y, x.y, a11);
        a12 = fmaf(w.y, x.z, a12); a13 = fmaf(w.y, x.w, a13);
        a20 = fmaf(w.z, x.x, a20); a21 = fmaf(w.z, x.y, a21);
        a22 = fmaf(w.z, x.z, a22); a23 = fmaf(w.z, x.w, a23);
        a30 = fmaf(w.w, x.x, a30); a31 = fmaf(w.w, x.y, a31);
        a32 = fmaf(w.w, x.z, a32); a33 = fmaf(w.w, x.w, a33);
    }

#define WROW(i, v0, v1, v2, v3)                                              \
    if (o0 + i < O) {                                                        \
        float bs = gb ? gb[o0 + i] : 0.f;                                    \
        float* yr = yb + (o0 + i) * 64 + t0;                                 \
        yr[0] = actf<ACT>(v0 + bs); yr[1] = actf<ACT>(v1 + bs);              \
        yr[2] = actf<ACT>(v2 + bs); yr[3] = actf<ACT>(v3 + bs);              \
    }
    WROW(0, a00, a01, a02, a03)
    WROW(1, a10, a11, a12, a13)
    WROW(2, a20, a21, a22, a23)
    WROW(3, a30, a31, a32, a33)
#undef WROW
}

// ---------------------------------------------------------------------------
// Kernel A: MotionEncoder + ConvGRU + fh1 + tpre
// SMEM floats: X[192*64] Y[4096] Z[4096] Nn[4096] W[192*68] FL[192] = 37824
// ---------------------------------------------------------------------------
#define SMEMA_FLOATS 37824

__global__ void __launch_bounds__(NTHR, 1) kernelA(
    const float* __restrict__ net, const float* __restrict__ inp,
    const float* __restrict__ corr, const float* __restrict__ flow,
    const float* __restrict__ w_corr, const float* __restrict__ b_corr,
    const float* __restrict__ w_flow, const float* __restrict__ b_flow,
    const float* __restrict__ w_me, const float* __restrict__ b_me,
    const float* __restrict__ wz, const float* __restrict__ bz,
    const float* __restrict__ wr, const float* __restrict__ br,
    const float* __restrict__ wq, const float* __restrict__ bq,
    const float* __restrict__ w_fh1, const float* __restrict__ b_fh1,
    const float* __restrict__ w_sc1,
    float* __restrict__ out_net) {
    extern __shared__ float sm[];
    float* X  = sm;            // 192*64 = 12288
    float* Y  = sm + 12288;    // 4096
    float* Z  = sm + 16384;    // 4096
    float* Nn = sm + 20480;    // 4096
    float* W  = sm + 24576;    // 192*68 = 13056
    float* FL = sm + 37632;    // 192

    const int tid = threadIdx.x;
    const int b = blockIdx.x / (NN / TILE);
    const int n0 = (blockIdx.x - b * (NN / TILE)) * TILE;

    // ---- loads ----
    load_cn(corr, b, n0, X);   // X rows 0..63 = corr
    load_cn(net, b, n0, Nn);
    for (int idx = tid; idx < 192; idx += NTHR)
        FL[idx] = flow[(size_t)(b * NN + n0) * 3 + idx];
    load_w(w_corr, 64, 64, 64, W);
    __syncthreads();

    // flo -> X rows 64..127
    for (int idx = tid; idx < 4096; idx += NTHR) {
        int o = idx >> 6, t = idx & 63;
        float v = b_flow[o];
        v = fmaf(w_flow[o * 3 + 0], FL[t * 3 + 0], v);
        v = fmaf(w_flow[o * 3 + 1], FL[t * 3 + 1], v);
        v = fmaf(w_flow[o * 3 + 2], FL[t * 3 + 2], v);
        X[(64 + o) * 64 + t] = fmaxf(v, 0.f);
    }
    gemm64<1>(X, 64, W, b_corr, 64, Y);          // cor
    __syncthreads();

    // ---- mf = relu(Wme @ [cor; flo]) ----
    for (int idx = tid; idx < 4096; idx += NTHR) X[idx] = Y[idx];  // cor
    load_w(w_me, 61, 128, 128, W);
    __syncthreads();
    gemm64<1>(X, 128, W, b_me, 61, Y);           // mf
    __syncthreads();

    // ---- hx = [net | inp | mf | flow] ----
    for (int idx = tid; idx < 4096; idx += NTHR) X[idx] = Nn[idx];
    load_cn(inp, b, n0, X + 64 * 64);
    for (int idx = tid; idx < 61 * 64; idx += NTHR) X[128 * 64 + idx] = Y[idx];
    for (int idx = tid; idx < 192; idx += NTHR) {
        int t = idx / 3, d = idx - t * 3;
        X[(189 + d) * 64 + t] = FL[idx];
    }
    load_w(wz, 64, 192, 192, W);
    __syncthreads();
    gemm64<2>(X, 192, W, bz, 64, Z);             // z
    __syncthreads();
    load_w(wr, 64, 192, 192, W);
    __syncthreads();
    gemm64<2>(X, 192, W, br, 64, Y);             // r
    __syncthreads();
    for (int idx = tid; idx < 4096; idx += NTHR) X[idx] = Y[idx] * Nn[idx];  // r*net
    load_w(wq, 64, 192, 192, W);
    __syncthreads();
    gemm64<3>(X, 192, W, bq, 64, Y);             // q
    __syncthreads();

    // ---- net_new = net + z*(q - net) ----
    for (int idx = tid; idx < 4096; idx += NTHR) {
        int o = idx >> 6, t = idx & 63;
        float v = fmaf(Z[idx], Y[idx] - Nn[idx], Nn[idx]);
        X[idx] = v;
        out_net[(size_t)(b * 64 + o) * NN + n0 + t] = v;
    }
    load_w(w_fh1, 64, 64, 64, W);
    __syncthreads();
    gemm64<0>(X, 64, W, b_fh1, 64, Y);           // o1 (no act)
    __syncthreads();
    for (int idx = tid; idx < 4096; idx += NTHR) {
        int o = idx >> 6, t = idx & 63;
        g_o1[(size_t)(b * 64 + o) * NN + n0 + t] = Y[idx];
    }
    load_w(w_sc1, 64, 64, 67, W);                // W1a = first 64 cols of w_sc1
    __syncthreads();
    gemm64<0>(X, 64, W, nullptr, 64, Z);         // tpre (no bias, no act)
    __syncthreads();
    for (int idx = tid; idx < 4096; idx += NTHR) {
        int t = idx >> 6, o = idx & 63;
        g_preT[(size_t)(b * NN + n0 + t) * 64 + o] = Z[o * 64 + t];
    }
}

// ---------------------------------------------------------------------------
// Kernel B: gather/max SetConv stage-1 (precomputed), sc2, sc3, out MLP
// SMEM floats: X[8192] Y[4096] MX[4096] W[8704] EF[3072] E[1024] = 29184
// ---------------------------------------------------------------------------
#define SMEMB_FLOATS 29184

__global__ void __launch_bounds__(NTHR, 1) kernelB(
    const int* __restrict__ edges, const float* __restrict__ ef,
    const float* __restrict__ w_sc1, const float* __restrict__ b_sc1,
    const float* __restrict__ w_sc2, const float* __restrict__ b_sc2,
    const float* __restrict__ w_sc3, const float* __restrict__ b_sc3,
    const float* __restrict__ w_out1, const float* __restrict__ b_out1,
    const float* __restrict__ w_out2, const float* __restrict__ b_out2,
    float* __restrict__ out_delta) {
    extern __shared__ float sm[];
    float* X  = sm;            // [sc(0..63) | o1(64..127)] x 64 = 8192
    float* Y  = sm + 8192;     // 4096
    float* MX = sm + 12288;    // 4096
    float* W  = sm + 16384;    // 128*68 = 8704
    float* EF = sm + 25088;    // 3072
    int*   E  = (int*)(sm + 28160);  // 1024 ints

    const int tid = threadIdx.x;
    const int b = blockIdx.x / (NN / TILE);
    const int n0 = (blockIdx.x - b * (NN / TILE)) * TILE;

    for (int idx = tid; idx < TILE * KK; idx += NTHR)
        E[idx] = edges[(size_t)(b * NN + n0) * KK + idx];
    for (int idx = tid; idx < TILE * KK * 3; idx += NTHR)
        EF[idx] = ef[(size_t)(b * NN + n0) * KK * 3 + idx];
    load_cn(g_o1, b, n0, X + 64 * 64);           // o1 -> X rows 64..127
    load_w(w_sc2, 64, 64, 64, W);                // preload for sc2
    __syncthreads();

    // ---- SetConv stage 1: m[o] = max_k(tpre[e_k][o] + W1b@ef_k); s = relu(m+b) ----
    {
        const int t = tid >> 2;       // point 0..63
        const int g = tid & 3;        // channel group
        const int oo = g * 16;

        float w3a[16], w3b[16], w3c[16];
#pragma unroll
        for (int i = 0; i < 16; i++) {
            const float* wr_ = w_sc1 + (oo + i) * 67 + 64;
            w3a[i] = wr_[0]; w3b[i] = wr_[1]; w3c[i] = wr_[2];
        }
        float m[16];
#pragma unroll
        for (int i = 0; i < 16; i++) m[i] = -FLT_MAX;

        const float4* gp = reinterpret_cast<const float4*>(g_preT);
#pragma unroll 1
        for (int k = 0; k < KK; k++) {
            int e = E[t * KK + k];
            const float* efp = EF + (t * KK + k) * 3;
            float e0 = efp[0], e1 = efp[1], e2 = efp[2];
            size_t base = (size_t)(b * NN + e) * 16 + (oo >> 2);
            float4 p0 = __ldg(gp + base + 0);
            float4 p1 = __ldg(gp + base + 1);
            float4 p2 = __ldg(gp + base + 2);
            float4 p3 = __ldg(gp + base + 3);
            float pv[16] = {p0.x, p0.y, p0.z, p0.w, p1.x, p1.y, p1.z, p1.w,
                            p2.x, p2.y, p2.z, p2.w, p3.x, p3.y, p3.z, p3.w};
#pragma unroll
            for (int i = 0; i < 16; i++) {
                float u = fmaf(w3a[i], e0, fmaf(w3b[i], e1, w3c[i] * e2));
                m[i] = fmaxf(m[i], pv[i] + u);
            }
        }
#pragma unroll
        for (int i = 0; i < 16; i++)
            MX[(oo + i) * 64 + t] = fmaxf(m[i] + b_sc1[oo + i], 0.f);
    }
    __syncthreads();

    // ---- sc2, sc3 ----
    gemm64<1>(MX, 64, W, b_sc2, 64, Y);
    __syncthreads();
    load_w(w_sc3, 64, 64, 64, W);
    __syncthreads();
    gemm64<1>(Y, 64, W, b_sc3, 64, X);           // sc -> X rows 0..63
    __syncthreads();

    // ---- out MLP ----
    load_w(w_out1, 64, 128, 128, W);
    __syncthreads();
    gemm64<1>(X, 128, W, b_out1, 64, Y);
    __syncthreads();
    load_w(w_out2, 3, 64, 64, W);
    __syncthreads();
    gemm64<0>(Y, 64, W, b_out2, 3, MX);          // delta rows 0..2
    __syncthreads();
    for (int idx = tid; idx < 192; idx += NTHR) {
        int t = idx / 3, d = idx - t * 3;
        out_delta[(size_t)(b * NN + n0 + t) * 3 + d] = MX[d * 64 + t];
    }
}

// ---------------------------------------------------------------------------
// Launch
// ---------------------------------------------------------------------------
extern "C" void kernel_launch(void* const* d_in, const int* in_sizes, int n_in,
                              void* d_out, int out_size) {
    const float* net    = (const float*)d_in[0];
    const float* inp    = (const float*)d_in[1];
    const float* corr   = (const float*)d_in[2];
    const float* flow   = (const float*)d_in[3];
    const int*   edges  = (const int*)d_in[4];
    const float* edgef  = (const float*)d_in[5];
    const float* w_corr = (const float*)d_in[6];
    const float* b_corr = (const float*)d_in[7];
    const float* w_flow = (const float*)d_in[8];
    const float* b_flow = (const float*)d_in[9];
    const float* w_me   = (const float*)d_in[10];
    const float* b_me   = (const float*)d_in[11];
    const float* wz     = (const float*)d_in[12];
    const float* bz     = (const float*)d_in[13];
    const float* wr     = (const float*)d_in[14];
    const float* br     = (const float*)d_in[15];
    const float* wq     = (const float*)d_in[16];
    const float* bq     = (const float*)d_in[17];
    const float* w_fh1  = (const float*)d_in[18];
    const float* b_fh1  = (const float*)d_in[19];
    const float* w_sc1  = (const float*)d_in[20];
    const float* b_sc1  = (const float*)d_in[21];
    const float* w_sc2  = (const float*)d_in[22];
    const float* b_sc2  = (const float*)d_in[23];
    const float* w_sc3  = (const float*)d_in[24];
    const float* b_sc3  = (const float*)d_in[25];
    const float* w_out1 = (const float*)d_in[26];
    const float* b_out1 = (const float*)d_in[27];
    const float* w_out2 = (const float*)d_in[28];
    const float* b_out2 = (const float*)d_in[29];

    float* out_net   = (float*)d_out;
    float* out_delta = (float*)d_out + (size_t)BB * 64 * NN;

    const int smemA = SMEMA_FLOATS * 4;
    const int smemB = SMEMB_FLOATS * 4;
    cudaFuncSetAttribute(kernelA, cudaFuncAttributeMaxDynamicSharedMemorySize, smemA);
    cudaFuncSetAttribute(kernelB, cudaFuncAttributeMaxDynamicSharedMemorySize, smemB);

    kernelA<<<NBLK, NTHR, smemA>>>(net, inp, corr, flow,
                                   w_corr, b_corr, w_flow, b_flow, w_me, b_me,
                                   wz, bz, wr, br, wq, bq, w_fh1, b_fh1, w_sc1,
                                   out_net);
    kernelB<<<NBLK, NTHR, smemB>>>(edges, edgef,
                                   w_sc1, b_sc1, w_sc2, b_sc2, w_sc3, b_sc3,
                                   w_out1, b_out1, w_out2, b_out2,
                                   out_delta);
}

// round 7
// speedup vs baseline: 1.9835x; 1.4585x over previous
#include <cuda_runtime.h>
#include <math.h>
#include <float.h>

#define BB 2
#define NN 32768
#define KK 16
#define TILE 128
#define NTHR 512
#define NBLK (BB * (NN / TILE))

// tpre = W1a @ net_new, transposed (B,N,64): neighbor feature vec is 256B contiguous.
__device__ float g_preT[(size_t)BB * NN * 64];
// o1 = w_fh1 @ net_new + b, layout (B,64,N).
__device__ float g_o1[(size_t)BB * 64 * NN];

template <int ACT>
__device__ __forceinline__ float actf(float v) {
    if (ACT == 1) return v > 0.f ? v : 0.f;
    if (ACT == 2) return 1.f / (1.f + __expf(-v));
    if (ACT == 3) return tanhf(v);
    return v;
}

// Load a 64-channel tile from a (B,64,N) tensor into SMEM [64][128].
__device__ __forceinline__ void load_cn(const float* __restrict__ g, int b, int n0,
                                        float* __restrict__ dst) {
    for (int idx = threadIdx.x; idx < 64 * TILE; idx += NTHR) {
        int c = idx >> 7, t = idx & 127;
        dst[idx] = g[(size_t)(b * 64 + c) * NN + n0 + t];
    }
}

// ---------------------------------------------------------------------------
// Tile GEMM over NB 64-row input blocks (C = NB*64), W staged in 64-col chunks.
// 512 threads: each owns 4 outputs x 4 points (2 LDS.128 : 16 FFMA per c).
// OUT=0: smem out[o*128+t];  OUT=1: global out + o*rstride + t (bias+act);
// OUT=2: global transposed out + t*64 + o (no bias/act).
// Contains its own __syncthreads (call from all threads, uniform args).
// ---------------------------------------------------------------------------
template <int ACT, int OUT, int NB>
__device__ __forceinline__ void gemmT(const float* const* xs,
                                      const float* __restrict__ wg, int O, int ld,
                                      const float* __restrict__ bias,
                                      float* __restrict__ Wst,
                                      float* __restrict__ out, size_t rstride) {
    const int tid = threadIdx.x;
    const int o0 = (tid >> 5) << 2;   // warp id * 4 : 0..60
    const int t0 = (tid & 31) << 2;   // lane * 4    : 0..124

    float a00 = 0.f, a01 = 0.f, a02 = 0.f, a03 = 0.f;
    float a10 = 0.f, a11 = 0.f, a12 = 0.f, a13 = 0.f;
    float a20 = 0.f, a21 = 0.f, a22 = 0.f, a23 = 0.f;
    float a30 = 0.f, a31 = 0.f, a32 = 0.f, a33 = 0.f;

#pragma unroll
    for (int blk = 0; blk < NB; blk++) {
        __syncthreads();   // prior Wst readers done; xs writes visible
        for (int idx = tid; idx < 4096; idx += NTHR) {
            int o = idx >> 6, c = idx & 63;
            Wst[c * 68 + o] = (o < O) ? wg[o * ld + blk * 64 + c] : 0.f;
        }
        __syncthreads();
        const float* xb = xs[blk];
#pragma unroll 4
        for (int c = 0; c < 64; c++) {
            float4 w = *(const float4*)(Wst + c * 68 + o0);
            float4 x = *(const float4*)(xb + c * 128 + t0);
            a00 = fmaf(w.x, x.x, a00); a01 = fmaf(w.x, x.y, a01);
            a02 = fmaf(w.x, x.z, a02); a03 = fmaf(w.x, x.w, a03);
            a10 = fmaf(w.y, x.x, a10); a11 = fmaf(w.y, x.y, a11);
            a12 = fmaf(w.y, x.z, a12); a13 = fmaf(w.y, x.w, a13);
            a20 = fmaf(w.z, x.x, a20); a21 = fmaf(w.z, x.y, a21);
            a22 = fmaf(w.z, x.z, a22); a23 = fmaf(w.z, x.w, a23);
            a30 = fmaf(w.w, x.x, a30); a31 = fmaf(w.w, x.y, a31);
            a32 = fmaf(w.w, x.z, a32); a33 = fmaf(w.w, x.w, a33);
        }
    }

    if (OUT == 2) {
        // transposed: row = point t, cols o0..o0+3.  Coalesced STG.128 per j.
        float* p = out + (size_t)t0 * 64 + o0;
        *(float4*)(p)       = make_float4(a00, a10, a20, a30);
        *(float4*)(p + 64)  = make_float4(a01, a11, a21, a31);
        *(float4*)(p + 128) = make_float4(a02, a12, a22, a32);
        *(float4*)(p + 192) = make_float4(a03, a13, a23, a33);
    } else {
#define WROW(i, v0, v1, v2, v3)                                               \
        if (o0 + i < O) {                                                     \
            float bs = bias ? bias[o0 + i] : 0.f;                             \
            float4 r = make_float4(actf<ACT>(v0 + bs), actf<ACT>(v1 + bs),    \
                                   actf<ACT>(v2 + bs), actf<ACT>(v3 + bs));   \
            if (OUT == 0) *(float4*)(out + (o0 + i) * 128 + t0) = r;          \
            else          *(float4*)(out + (size_t)(o0 + i) * rstride + t0) = r; \
        }
        WROW(0, a00, a01, a02, a03)
        WROW(1, a10, a11, a12, a13)
        WROW(2, a20, a21, a22, a23)
        WROW(3, a30, a31, a32, a33)
#undef WROW
    }
}

// ---------------------------------------------------------------------------
// Kernel A: MotionEncoder + ConvGRU + fh1 + tpre
// SMEM floats: P0..P5 6*8192 + W 4352 + FL 384 = 53888  (215.5 KB)
// ---------------------------------------------------------------------------
#define SMEMA_FLOATS 53888

__global__ void __launch_bounds__(NTHR, 1) kernelA(
    const float* __restrict__ net, const float* __restrict__ inp,
    const float* __restrict__ corr, const float* __restrict__ flow,
    const float* __restrict__ w_corr, const float* __restrict__ b_corr,
    const float* __restrict__ w_flow, const float* __restrict__ b_flow,
    const float* __restrict__ w_me, const float* __restrict__ b_me,
    const float* __restrict__ wz, const float* __restrict__ bz,
    const float* __restrict__ wr, const float* __restrict__ br,
    const float* __restrict__ wq, const float* __restrict__ bq,
    const float* __restrict__ w_fh1, const float* __restrict__ b_fh1,
    const float* __restrict__ w_sc1,
    float* __restrict__ out_net) {
    extern __shared__ float sm[];
    float* P0 = sm;              // corr -> z
    float* P1 = sm + 8192;       // flo -> r -> r*net
    float* P2 = sm + 16384;      // cor -> q
    float* P3 = sm + 24576;      // mff (mf rows 0..60, flow rows 61..63)
    float* P4 = sm + 32768;      // net -> net_new
    float* P5 = sm + 40960;      // inp
    float* W  = sm + 49152;      // 64*68 = 4352
    float* FL = sm + 53504;      // 384

    const int tid = threadIdx.x;
    const int b = blockIdx.x / (NN / TILE);
    const int n0 = (blockIdx.x - b * (NN / TILE)) * TILE;

    load_cn(corr, b, n0, P0);
    load_cn(net, b, n0, P4);
    load_cn(inp, b, n0, P5);
    for (int idx = tid; idx < TILE * 3; idx += NTHR)
        FL[idx] = flow[(size_t)(b * NN + n0) * 3 + idx];
    __syncthreads();

    // flo -> P1
    for (int idx = tid; idx < 8192; idx += NTHR) {
        int o = idx >> 7, t = idx & 127;
        float v = b_flow[o];
        v = fmaf(w_flow[o * 3 + 0], FL[t * 3 + 0], v);
        v = fmaf(w_flow[o * 3 + 1], FL[t * 3 + 1], v);
        v = fmaf(w_flow[o * 3 + 2], FL[t * 3 + 2], v);
        P1[o * 128 + t] = fmaxf(v, 0.f);
    }
    {   // cor = relu(Wc @ corr)
        const float* xs[1] = {P0};
        gemmT<1, 0, 1>(xs, w_corr, 64, 64, b_corr, W, P2, 0);
    }
    {   // mf = relu(Wme @ [cor; flo])
        const float* xs[2] = {P2, P1};
        gemmT<1, 0, 2>(xs, w_me, 61, 128, b_me, W, P3, 0);
    }
    // flow rows 61..63 of mff (disjoint from mf rows; next gemm syncs before read)
    for (int idx = tid; idx < TILE * 3; idx += NTHR) {
        int t = idx / 3, d = idx - t * 3;
        P3[(61 + d) * 128 + t] = FL[idx];
    }
    {   // z
        const float* xs[3] = {P4, P5, P3};
        gemmT<2, 0, 3>(xs, wz, 64, 192, bz, W, P0, 0);
    }
    {   // r
        const float* xs[3] = {P4, P5, P3};
        gemmT<2, 0, 3>(xs, wr, 64, 192, br, W, P1, 0);
    }
    __syncthreads();
    for (int idx = tid; idx < 8192; idx += NTHR) P1[idx] *= P4[idx];  // r*net
    {   // q
        const float* xs[3] = {P1, P5, P3};
        gemmT<3, 0, 3>(xs, wq, 64, 192, bq, W, P2, 0);
    }
    __syncthreads();
    // net_new = net + z*(q - net)  (in place in P4) + store
    for (int idx = tid; idx < 8192; idx += NTHR) {
        int o = idx >> 7, t = idx & 127;
        float v = fmaf(P0[idx], P2[idx] - P4[idx], P4[idx]);
        P4[idx] = v;
        out_net[(size_t)(b * 64 + o) * NN + n0 + t] = v;
    }
    {   // o1 -> g_o1 rows (coalesced STG.128 from registers)
        const float* xs[1] = {P4};
        gemmT<0, 1, 1>(xs, w_fh1, 64, 64, b_fh1, W,
                       g_o1 + (size_t)(b * 64) * NN + n0, NN);
    }
    {   // tpre -> g_preT transposed (no bias/act)
        const float* xs[1] = {P4};
        gemmT<0, 2, 1>(xs, w_sc1, 64, 67, nullptr, W,
                       g_preT + (size_t)(b * NN + n0) * 64, 0);
    }
}

// ---------------------------------------------------------------------------
// Kernel B: gather/max SetConv stage-1 (precomputed), sc2, sc3, out MLP
// SMEM floats: MX,Y,SC,O1b 4*8192 + W 4352 + EF 6144 + E 2048 = 45312 (181 KB)
// ---------------------------------------------------------------------------
#define SMEMB_FLOATS 45312

__global__ void __launch_bounds__(NTHR, 1) kernelB(
    const int* __restrict__ edges, const float* __restrict__ ef,
    const float* __restrict__ w_sc1, const float* __restrict__ b_sc1,
    const float* __restrict__ w_sc2, const float* __restrict__ b_sc2,
    const float* __restrict__ w_sc3, const float* __restrict__ b_sc3,
    const float* __restrict__ w_out1, const float* __restrict__ b_out1,
    const float* __restrict__ w_out2, const float* __restrict__ b_out2,
    float* __restrict__ out_delta) {
    extern __shared__ float sm[];
    float* MX  = sm;             // stage1 out -> out1 out
    float* Y   = sm + 8192;      // sc2 out -> out2 out
    float* SC  = sm + 16384;     // sc3 out
    float* O1b = sm + 24576;     // o1 tile
    float* W   = sm + 32768;     // 4352
    float* EF  = sm + 37120;     // 6144
    int*   E   = (int*)(sm + 43264);  // 2048 ints

    const int tid = threadIdx.x;
    const int b = blockIdx.x / (NN / TILE);
    const int n0 = (blockIdx.x - b * (NN / TILE)) * TILE;

    for (int idx = tid; idx < TILE * KK; idx += NTHR)
        E[idx] = edges[(size_t)(b * NN + n0) * KK + idx];
    for (int idx = tid; idx < TILE * KK * 3; idx += NTHR)
        EF[idx] = ef[(size_t)(b * NN + n0) * KK * 3 + idx];
    load_cn(g_o1, b, n0, O1b);
    __syncthreads();

    // ---- stage 1: m[o] = max_k(tpre[e_k][o] + W1b@ef_k); MX = relu(m + b1) ----
    {
        const int t = tid >> 2;       // 0..127
        const int g = tid & 3;
        const int oo = g * 16;

        float w3a[16], w3b[16], w3c[16];
#pragma unroll
        for (int i = 0; i < 16; i++) {
            const float* wr_ = w_sc1 + (oo + i) * 67 + 64;
            w3a[i] = wr_[0]; w3b[i] = wr_[1]; w3c[i] = wr_[2];
        }
        float m[16];
#pragma unroll
        for (int i = 0; i < 16; i++) m[i] = -FLT_MAX;

        const float4* gp = reinterpret_cast<const float4*>(g_preT);
#pragma unroll 1
        for (int k = 0; k < KK; k++) {
            int e = E[t * KK + k];
            const float* efp = EF + (t * KK + k) * 3;
            float e0 = efp[0], e1 = efp[1], e2 = efp[2];
            size_t base = (size_t)(b * NN + e) * 16 + (oo >> 2);
            float4 p0 = __ldg(gp + base + 0);
            float4 p1 = __ldg(gp + base + 1);
            float4 p2 = __ldg(gp + base + 2);
            float4 p3 = __ldg(gp + base + 3);
            float pv[16] = {p0.x, p0.y, p0.z, p0.w, p1.x, p1.y, p1.z, p1.w,
                            p2.x, p2.y, p2.z, p2.w, p3.x, p3.y, p3.z, p3.w};
#pragma unroll
            for (int i = 0; i < 16; i++) {
                float u = fmaf(w3a[i], e0, fmaf(w3b[i], e1, w3c[i] * e2));
                m[i] = fmaxf(m[i], pv[i] + u);
            }
        }
#pragma unroll
        for (int i = 0; i < 16; i++)
            MX[(oo + i) * 128 + t] = fmaxf(m[i] + b_sc1[oo + i], 0.f);
    }

    {   // sc2
        const float* xs[1] = {MX};
        gemmT<1, 0, 1>(xs, w_sc2, 64, 64, b_sc2, W, Y, 0);
    }
    {   // sc3
        const float* xs[1] = {Y};
        gemmT<1, 0, 1>(xs, w_sc3, 64, 64, b_sc3, W, SC, 0);
    }
    {   // out1 on [sc; o1]
        const float* xs[2] = {SC, O1b};
        gemmT<1, 0, 2>(xs, w_out1, 64, 128, b_out1, W, MX, 0);
    }
    {   // out2 -> delta rows 0..2
        const float* xs[1] = {MX};
        gemmT<0, 0, 1>(xs, w_out2, 3, 64, b_out2, W, Y, 0);
    }
    __syncthreads();
    for (int idx = tid; idx < TILE * 3; idx += NTHR) {
        int t = idx / 3, d = idx - t * 3;
        out_delta[(size_t)(b * NN + n0 + t) * 3 + d] = Y[d * 128 + t];
    }
}

// ---------------------------------------------------------------------------
// Launch
// ---------------------------------------------------------------------------
extern "C" void kernel_launch(void* const* d_in, const int* in_sizes, int n_in,
                              void* d_out, int out_size) {
    const float* net    = (const float*)d_in[0];
    const float* inp    = (const float*)d_in[1];
    const float* corr   = (const float*)d_in[2];
    const float* flow   = (const float*)d_in[3];
    const int*   edges  = (const int*)d_in[4];
    const float* edgef  = (const float*)d_in[5];
    const float* w_corr = (const float*)d_in[6];
    const float* b_corr = (const float*)d_in[7];
    const float* w_flow = (const float*)d_in[8];
    const float* b_flow = (const float*)d_in[9];
    const float* w_me   = (const float*)d_in[10];
    const float* b_me   = (const float*)d_in[11];
    const float* wz     = (const float*)d_in[12];
    const float* bz     = (const float*)d_in[13];
    const float* wr     = (const float*)d_in[14];
    const float* br     = (const float*)d_in[15];
    const float* wq     = (const float*)d_in[16];
    const float* bq     = (const float*)d_in[17];
    const float* w_fh1  = (const float*)d_in[18];
    const float* b_fh1  = (const float*)d_in[19];
    const float* w_sc1  = (const float*)d_in[20];
    const float* b_sc1  = (const float*)d_in[21];
    const float* w_sc2  = (const float*)d_in[22];
    const float* b_sc2  = (const float*)d_in[23];
    const float* w_sc3  = (const float*)d_in[24];
    const float* b_sc3  = (const float*)d_in[25];
    const float* w_out1 = (const float*)d_in[26];
    const float* b_out1 = (const float*)d_in[27];
    const float* w_out2 = (const float*)d_in[28];
    const float* b_out2 = (const float*)d_in[29];

    float* out_net   = (float*)d_out;
    float* out_delta = (float*)d_out + (size_t)BB * 64 * NN;

    const int smemA = SMEMA_FLOATS * 4;
    const int smemB = SMEMB_FLOATS * 4;
    cudaFuncSetAttribute(kernelA, cudaFuncAttributeMaxDynamicSharedMemorySize, smemA);
    cudaFuncSetAttribute(kernelB, cudaFuncAttributeMaxDynamicSharedMemorySize, smemB);

    kernelA<<<NBLK, NTHR, smemA>>>(net, inp, corr, flow,
                                   w_corr, b_corr, w_flow, b_flow, w_me, b_me,
                                   wz, bz, wr, br, wq, bq, w_fh1, b_fh1, w_sc1,
                                   out_net);
    kernelB<<<NBLK, NTHR, smemB>>>(edges, edgef,
                                   w_sc1, b_sc1, w_sc2, b_sc2, w_sc3, b_sc3,
                                   w_out1, b_out1, w_out2, b_out2,
                                   out_delta);
}

// round 9
// speedup vs baseline: 2.1491x; 1.0835x over previous
#include <cuda_runtime.h>
#include <math.h>
#include <float.h>

#define BB 2
#define NN 32768
#define KK 16
#define TILE 128
#define NTHR 512
#define NBLK (BB * (NN / TILE))

typedef unsigned long long u64;

// tpre = W1a @ net_new, transposed (B,N,64): neighbor feature vec is 256B contiguous.
__device__ float g_preT[(size_t)BB * NN * 64];
// o1 = w_fh1 @ net_new + b, layout (B,64,N).
__device__ float g_o1[(size_t)BB * 64 * NN];

template <int ACT>
__device__ __forceinline__ float actf(float v) {
    if (ACT == 1) return v > 0.f ? v : 0.f;
    if (ACT == 2) return 1.f / (1.f + __expf(-v));
    if (ACT == 3) return tanhf(v);
    return v;
}

// Load a 64-channel tile from a (B,64,N) tensor into SMEM [64][128].
__device__ __forceinline__ void load_cn(const float* __restrict__ g, int b, int n0,
                                        float* __restrict__ dst) {
    for (int idx = threadIdx.x; idx < 64 * TILE; idx += NTHR) {
        int c = idx >> 7, t = idx & 127;
        dst[idx] = g[(size_t)(b * 64 + c) * NN + n0 + t];
    }
}

__device__ __forceinline__ u64 pack2(float v) {
    u64 r;
    asm("mov.b64 %0, {%1, %1};" : "=l"(r) : "r"(__float_as_uint(v)));
    return r;
}
__device__ __forceinline__ void fma2(u64& acc, u64 a, u64 b) {
    asm("fma.rn.f32x2 %0, %1, %2, %0;" : "+l"(acc) : "l"(a), "l"(b));
}
__device__ __forceinline__ void unpack2(u64 p, float& lo, float& hi) {
    unsigned int l, h;
    asm("mov.b64 {%0, %1}, %2;" : "=r"(l), "=r"(h) : "l"(p));
    lo = __uint_as_float(l); hi = __uint_as_float(h);
}

// ---------------------------------------------------------------------------
// Tile GEMM over NB 64-row input blocks (C = NB*64), W staged in 64-col chunks.
// 512 threads: each owns 4 outputs x 4 points.  Inner loop uses packed
// fma.rn.f32x2: 2 LDS.128 + 4 pack + 8 FFMA2 per c (was 16 FFMA).
// OUT=0: smem out[o*128+t];  OUT=1: global out + o*rstride + t (bias+act);
// OUT=2: global transposed out + t*64 + o (no bias/act).
// Contains its own __syncthreads (call from all threads, uniform args).
// ---------------------------------------------------------------------------
template <int ACT, int OUT, int NB>
__device__ __forceinline__ void gemmT(const float* const* xs,
                                      const float* __restrict__ wg, int O, int ld,
                                      const float* __restrict__ bias,
                                      float* __restrict__ Wst,
                                      float* __restrict__ out, size_t rstride) {
    const int tid = threadIdx.x;
    const int o0 = (tid >> 5) << 2;   // warp id * 4 : 0..60
    const int t0 = (tid & 31) << 2;   // lane * 4    : 0..124

    u64 p00 = 0, p01 = 0, p10 = 0, p11 = 0;
    u64 p20 = 0, p21 = 0, p30 = 0, p31 = 0;

#pragma unroll
    for (int blk = 0; blk < NB; blk++) {
        __syncthreads();   // prior Wst readers done; xs writes visible
        for (int idx = tid; idx < 4096; idx += NTHR) {
            int o = idx >> 6, c = idx & 63;
            Wst[c * 68 + o] = (o < O) ? wg[o * ld + blk * 64 + c] : 0.f;
        }
        __syncthreads();
        const float* xb = xs[blk];
#pragma unroll 4
        for (int c = 0; c < 64; c++) {
            float4 w = *(const float4*)(Wst + c * 68 + o0);
            const u64* xp = (const u64*)(xb + c * 128 + t0);
            u64 x0 = xp[0], x1 = xp[1];
            u64 wp0 = pack2(w.x), wp1 = pack2(w.y);
            u64 wp2 = pack2(w.z), wp3 = pack2(w.w);
            fma2(p00, wp0, x0); fma2(p01, wp0, x1);
            fma2(p10, wp1, x0); fma2(p11, wp1, x1);
            fma2(p20, wp2, x0); fma2(p21, wp2, x1);
            fma2(p30, wp3, x0); fma2(p31, wp3, x1);
        }
    }

    float a00, a01, a02, a03, a10, a11, a12, a13;
    float a20, a21, a22, a23, a30, a31, a32, a33;
    unpack2(p00, a00, a01); unpack2(p01, a02, a03);
    unpack2(p10, a10, a11); unpack2(p11, a12, a13);
    unpack2(p20, a20, a21); unpack2(p21, a22, a23);
    unpack2(p30, a30, a31); unpack2(p31, a32, a33);

    if (OUT == 2) {
        // transposed: row = point t, cols o0..o0+3.  Coalesced STG.128 per j.
        float* p = out + (size_t)t0 * 64 + o0;
        *(float4*)(p)       = make_float4(a00, a10, a20, a30);
        *(float4*)(p + 64)  = make_float4(a01, a11, a21, a31);
        *(float4*)(p + 128) = make_float4(a02, a12, a22, a32);
        *(float4*)(p + 192) = make_float4(a03, a13, a23, a33);
    } else {
#define WROW(i, v0, v1, v2, v3)                                               \
        if (o0 + i < O) {                                                     \
            float bs = bias ? bias[o0 + i] : 0.f;                             \
            float4 r = make_float4(actf<ACT>(v0 + bs), actf<ACT>(v1 + bs),    \
                                   actf<ACT>(v2 + bs), actf<ACT>(v3 + bs));   \
            if (OUT == 0) *(float4*)(out + (o0 + i) * 128 + t0) = r;          \
            else          *(float4*)(out + (size_t)(o0 + i) * rstride + t0) = r; \
        }
        WROW(0, a00, a01, a02, a03)
        WROW(1, a10, a11, a12, a13)
        WROW(2, a20, a21, a22, a23)
        WROW(3, a30, a31, a32, a33)
#undef WROW
    }
}

// ---------------------------------------------------------------------------
// Kernel A: MotionEncoder + ConvGRU + fh1 + tpre
// SMEM floats: P0..P5 6*8192 + W 4352 + FL 384 = 53888  (215.5 KB)
// ---------------------------------------------------------------------------
#define SMEMA_FLOATS 53888

__global__ void __launch_bounds__(NTHR, 1) kernelA(
    const float* __restrict__ net, const float* __restrict__ inp,
    const float* __restrict__ corr, const float* __restrict__ flow,
    const float* __restrict__ w_corr, const float* __restrict__ b_corr,
    const float* __restrict__ w_flow, const float* __restrict__ b_flow,
    const float* __restrict__ w_me, const float* __restrict__ b_me,
    const float* __restrict__ wz, const float* __restrict__ bz,
    const float* __restrict__ wr, const float* __restrict__ br,
    const float* __restrict__ wq, const float* __restrict__ bq,
    const float* __restrict__ w_fh1, const float* __restrict__ b_fh1,
    const float* __restrict__ w_sc1,
    float* __restrict__ out_net) {
    extern __shared__ float sm[];
    float* P0 = sm;              // corr -> z
    float* P1 = sm + 8192;       // flo -> r -> r*net
    float* P2 = sm + 16384;      // cor -> q
    float* P3 = sm + 24576;      // mff (mf rows 0..60, flow rows 61..63)
    float* P4 = sm + 32768;      // net -> net_new
    float* P5 = sm + 40960;      // inp
    float* W  = sm + 49152;      // 64*68 = 4352
    float* FL = sm + 53504;      // 384

    const int tid = threadIdx.x;
    const int b = blockIdx.x / (NN / TILE);
    const int n0 = (blockIdx.x - b * (NN / TILE)) * TILE;

    load_cn(corr, b, n0, P0);
    load_cn(net, b, n0, P4);
    load_cn(inp, b, n0, P5);
    for (int idx = tid; idx < TILE * 3; idx += NTHR)
        FL[idx] = flow[(size_t)(b * NN + n0) * 3 + idx];
    __syncthreads();

    // flo -> P1
    for (int idx = tid; idx < 8192; idx += NTHR) {
        int o = idx >> 7, t = idx & 127;
        float v = b_flow[o];
        v = fmaf(w_flow[o * 3 + 0], FL[t * 3 + 0], v);
        v = fmaf(w_flow[o * 3 + 1], FL[t * 3 + 1], v);
        v = fmaf(w_flow[o * 3 + 2], FL[t * 3 + 2], v);
        P1[o * 128 + t] = fmaxf(v, 0.f);
    }
    {   // cor = relu(Wc @ corr)
        const float* xs[1] = {P0};
        gemmT<1, 0, 1>(xs, w_corr, 64, 64, b_corr, W, P2, 0);
    }
    {   // mf = relu(Wme @ [cor; flo])
        const float* xs[2] = {P2, P1};
        gemmT<1, 0, 2>(xs, w_me, 61, 128, b_me, W, P3, 0);
    }
    // flow rows 61..63 of mff (disjoint from mf rows; next gemm syncs before read)
    for (int idx = tid; idx < TILE * 3; idx += NTHR) {
        int t = idx / 3, d = idx - t * 3;
        P3[(61 + d) * 128 + t] = FL[idx];
    }
    {   // z
        const float* xs[3] = {P4, P5, P3};
        gemmT<2, 0, 3>(xs, wz, 64, 192, bz, W, P0, 0);
    }
    {   // r
        const float* xs[3] = {P4, P5, P3};
        gemmT<2, 0, 3>(xs, wr, 64, 192, br, W, P1, 0);
    }
    __syncthreads();
    for (int idx = tid; idx < 8192; idx += NTHR) P1[idx] *= P4[idx];  // r*net
    {   // q
        const float* xs[3] = {P1, P5, P3};
        gemmT<3, 0, 3>(xs, wq, 64, 192, bq, W, P2, 0);
    }
    __syncthreads();
    // net_new = net + z*(q - net)  (in place in P4) + store
    for (int idx = tid; idx < 8192; idx += NTHR) {
        int o = idx >> 7, t = idx & 127;
        float v = fmaf(P0[idx], P2[idx] - P4[idx], P4[idx]);
        P4[idx] = v;
        out_net[(size_t)(b * 64 + o) * NN + n0 + t] = v;
    }
    {   // o1 -> g_o1 rows (coalesced STG.128 from registers)
        const float* xs[1] = {P4};
        gemmT<0, 1, 1>(xs, w_fh1, 64, 64, b_fh1, W,
                       g_o1 + (size_t)(b * 64) * NN + n0, NN);
    }
    {   // tpre -> g_preT transposed (no bias/act)
        const float* xs[1] = {P4};
        gemmT<0, 2, 1>(xs, w_sc1, 64, 67, nullptr, W,
                       g_preT + (size_t)(b * NN + n0) * 64, 0);
    }
}

// ---------------------------------------------------------------------------
// Kernel B: gather/max SetConv stage-1 (precomputed), sc2, sc3, out MLP
// SMEM floats: MX,Y,SC,O1b 4*8192 + W 4352 + EF 6144 + E 2048 = 45312 (181 KB)
// ---------------------------------------------------------------------------
#define SMEMB_FLOATS 45312

__global__ void __launch_bounds__(NTHR, 1) kernelB(
    const int* __restrict__ edges, const float* __restrict__ ef,
    const float* __restrict__ w_sc1, const float* __restrict__ b_sc1,
    const float* __restrict__ w_sc2, const float* __restrict__ b_sc2,
    const float* __restrict__ w_sc3, const float* __restrict__ b_sc3,
    const float* __restrict__ w_out1, const float* __restrict__ b_out1,
    const float* __restrict__ w_out2, const float* __restrict__ b_out2,
    float* __restrict__ out_delta) {
    extern __shared__ float sm[];
    float* MX  = sm;             // stage1 out -> out1 out
    float* Y   = sm + 8192;      // sc2 out -> out2 out
    float* SC  = sm + 16384;     // sc3 out
    float* O1b = sm + 24576;     // o1 tile
    float* W   = sm + 32768;     // 4352
    float* EF  = sm + 37120;     // 6144
    int*   E   = (int*)(sm + 43264);  // 2048 ints

    const int tid = threadIdx.x;
    const int b = blockIdx.x / (NN / TILE);
    const int n0 = (blockIdx.x - b * (NN / TILE)) * TILE;

    for (int idx = tid; idx < TILE * KK; idx += NTHR)
        E[idx] = edges[(size_t)(b * NN + n0) * KK + idx];
    for (int idx = tid; idx < TILE * KK * 3; idx += NTHR)
        EF[idx] = ef[(size_t)(b * NN + n0) * KK * 3 + idx];
    load_cn(g_o1, b, n0, O1b);
    __syncthreads();

    // ---- stage 1: m[o] = max_k(tpre[e_k][o] + W1b@ef_k); MX = relu(m + b1) ----
    {
        const int t = tid >> 2;       // 0..127
        const int g = tid & 3;
        const int oo = g * 16;

        float w3a[16], w3b[16], w3c[16];
#pragma unroll
        for (int i = 0; i < 16; i++) {
            const float* wr_ = w_sc1 + (oo + i) * 67 + 64;
            w3a[i] = wr_[0]; w3b[i] = wr_[1]; w3c[i] = wr_[2];
        }
        float m[16];
#pragma unroll
        for (int i = 0; i < 16; i++) m[i] = -FLT_MAX;

        const float4* gp = reinterpret_cast<const float4*>(g_preT);
#pragma unroll 1
        for (int k = 0; k < KK; k++) {
            int e = E[t * KK + k];
            const float* efp = EF + (t * KK + k) * 3;
            float e0 = efp[0], e1 = efp[1], e2 = efp[2];
            size_t base = (size_t)(b * NN + e) * 16 + (oo >> 2);
            float4 p0 = __ldg(gp + base + 0);
            float4 p1 = __ldg(gp + base + 1);
            float4 p2 = __ldg(gp + base + 2);
            float4 p3 = __ldg(gp + base + 3);
            float pv[16] = {p0.x, p0.y, p0.z, p0.w, p1.x, p1.y, p1.z, p1.w,
                            p2.x, p2.y, p2.z, p2.w, p3.x, p3.y, p3.z, p3.w};
#pragma unroll
            for (int i = 0; i < 16; i++) {
                float u = fmaf(w3a[i], e0, fmaf(w3b[i], e1, w3c[i] * e2));
                m[i] = fmaxf(m[i], pv[i] + u);
            }
        }
#pragma unroll
        for (int i = 0; i < 16; i++)
            MX[(oo + i) * 128 + t] = fmaxf(m[i] + b_sc1[oo + i], 0.f);
    }

    {   // sc2
        const float* xs[1] = {MX};
        gemmT<1, 0, 1>(xs, w_sc2, 64, 64, b_sc2, W, Y, 0);
    }
    {   // sc3
        const float* xs[1] = {Y};
        gemmT<1, 0, 1>(xs, w_sc3, 64, 64, b_sc3, W, SC, 0);
    }
    {   // out1 on [sc; o1]
        const float* xs[2] = {SC, O1b};
        gemmT<1, 0, 2>(xs, w_out1, 64, 128, b_out1, W, MX, 0);
    }
    {   // out2 -> delta rows 0..2
        const float* xs[1] = {MX};
        gemmT<0, 0, 1>(xs, w_out2, 3, 64, b_out2, W, Y, 0);
    }
    __syncthreads();
    for (int idx = tid; idx < TILE * 3; idx += NTHR) {
        int t = idx / 3, d = idx - t * 3;
        out_delta[(size_t)(b * NN + n0 + t) * 3 + d] = Y[d * 128 + t];
    }
}

// ---------------------------------------------------------------------------
// Launch
// ---------------------------------------------------------------------------
extern "C" void kernel_launch(void* const* d_in, const int* in_sizes, int n_in,
                              void* d_out, int out_size) {
    const float* net    = (const float*)d_in[0];
    const float* inp    = (const float*)d_in[1];
    const float* corr   = (const float*)d_in[2];
    const float* flow   = (const float*)d_in[3];
    const int*   edges  = (const int*)d_in[4];
    const float* edgef  = (const float*)d_in[5];
    const float* w_corr = (const float*)d_in[6];
    const float* b_corr = (const float*)d_in[7];
    const float* w_flow = (const float*)d_in[8];
    const float* b_flow = (const float*)d_in[9];
    const float* w_me   = (const float*)d_in[10];
    const float* b_me   = (const float*)d_in[11];
    const float* wz     = (const float*)d_in[12];
    const float* bz     = (const float*)d_in[13];
    const float* wr     = (const float*)d_in[14];
    const float* br     = (const float*)d_in[15];
    const float* wq     = (const float*)d_in[16];
    const float* bq     = (const float*)d_in[17];
    const float* w_fh1  = (const float*)d_in[18];
    const float* b_fh1  = (const float*)d_in[19];
    const float* w_sc1  = (const float*)d_in[20];
    const float* b_sc1  = (const float*)d_in[21];
    const float* w_sc2  = (const float*)d_in[22];
    const float* b_sc2  = (const float*)d_in[23];
    const float* w_sc3  = (const float*)d_in[24];
    const float* b_sc3  = (const float*)d_in[25];
    const float* w_out1 = (const float*)d_in[26];
    const float* b_out1 = (const float*)d_in[27];
    const float* w_out2 = (const float*)d_in[28];
    const float* b_out2 = (const float*)d_in[29];

    float* out_net   = (float*)d_out;
    float* out_delta = (float*)d_out + (size_t)BB * 64 * NN;

    const int smemA = SMEMA_FLOATS * 4;
    const int smemB = SMEMB_FLOATS * 4;
    cudaFuncSetAttribute(kernelA, cudaFuncAttributeMaxDynamicSharedMemorySize, smemA);
    cudaFuncSetAttribute(kernelB, cudaFuncAttributeMaxDynamicSharedMemorySize, smemB);

    kernelA<<<NBLK, NTHR, smemA>>>(net, inp, corr, flow,
                                   w_corr, b_corr, w_flow, b_flow, w_me, b_me,
                                   wz, bz, wr, br, wq, bq, w_fh1, b_fh1, w_sc1,
                                   out_net);
    kernelB<<<NBLK, NTHR, smemB>>>(edges, edgef,
                                   w_sc1, b_sc1, w_sc2, b_sc2, w_sc3, b_sc3,
                                   w_out1, b_out1, w_out2, b_out2,
                                   out_delta);
}